// round 7
// baseline (speedup 1.0000x reference)
#include <cuda_runtime.h>
#include <math_constants.h>

// NDE loss:
//   lse_ori[b,t] = logsumexp_V(ori[b,t,:])      (B0*T rows)
//   lse_gen[n,t] = logsumexp_V(gen[n,t,:])      (N*T rows)
//   rep[n] = repeat_interleave(arange(B0), masked_item_lens)[n]
//   out = (1/(N*E*T)) * sum_{n,t,e} ( gen[n,t,ent[n,e]] - ori[rep[n],t,ent[n,e]] )
//       + (1/(N*T))   * sum_{n,t}   ( lse_ori[rep[n],t] - lse_gen[n,t] )
//
// Bench shapes: B0=8, N=16, T=128, V=50257, E=4. T,V hardcoded; B0,N,E from in_sizes.

#define T_DIM 128
#define V_DIM 50257
#define NTHREADS 256

// Static scratch (no allocations allowed). Generous upper bounds.
__device__ float g_lse_ori[64 * T_DIM];
__device__ float g_lse_gen[128 * T_DIM];

// ---------------------------------------------------------------------------
// Kernel 1: one block per (tensor-row). Online logsumexp, 4-wide batched
// rescale (5 exps / 4 elements) to keep MUFU below the HBM roofline.
// ---------------------------------------------------------------------------
__global__ void __launch_bounds__(NTHREADS)
lse_kernel(const float* __restrict__ ori, const float* __restrict__ gen,
           int B0, int N) {
    const int row = blockIdx.x;
    const int oriRows = B0 * T_DIM;

    const float* base;
    float* out;
    if (row < oriRows) {
        base = ori + (size_t)row * V_DIM;
        out = &g_lse_ori[row];
    } else {
        const int rr = row - oriRows;
        base = gen + (size_t)rr * V_DIM;
        out = &g_lse_gen[rr];
    }

    const int tid = threadIdx.x;
    const int B = NTHREADS;

    float m = -CUDART_INF_F;
    float s = 0.0f;

    int j = tid;
    // Batched: elements j, j+B, j+2B, j+3B per iteration (coalesced per warp).
    #pragma unroll 4
    for (; j + 3 * B < V_DIM; j += 4 * B) {
        float x0 = base[j];
        float x1 = base[j + B];
        float x2 = base[j + 2 * B];
        float x3 = base[j + 3 * B];
        float lm = fmaxf(fmaxf(x0, x1), fmaxf(x2, x3));
        float nm = fmaxf(m, lm);
        s = s * __expf(m - nm)
            + __expf(x0 - nm) + __expf(x1 - nm)
            + __expf(x2 - nm) + __expf(x3 - nm);
        m = nm;
    }
    // Tail.
    for (; j < V_DIM; j += B) {
        float x = base[j];
        float nm = fmaxf(m, x);
        s = s * __expf(m - nm) + __expf(x - nm);
        m = nm;
    }

    // Warp-level (m, s) merge.
    const unsigned full = 0xffffffffu;
    #pragma unroll
    for (int off = 16; off; off >>= 1) {
        float om = __shfl_xor_sync(full, m, off);
        float os = __shfl_xor_sync(full, s, off);
        float nm = fmaxf(m, om);
        s = s * __expf(m - nm) + os * __expf(om - nm);
        m = nm;
    }

    __shared__ float shm[NTHREADS / 32];
    __shared__ float shs[NTHREADS / 32];
    const int wid = tid >> 5;
    const int lane = tid & 31;
    if (lane == 0) { shm[wid] = m; shs[wid] = s; }
    __syncthreads();

    if (tid == 0) {
        float M = shm[0];
        float S = shs[0];
        #pragma unroll
        for (int w = 1; w < NTHREADS / 32; w++) {
            float om = shm[w], os = shs[w];
            float nm = fmaxf(M, om);
            S = S * __expf(M - nm) + os * __expf(om - nm);
            M = nm;
        }
        *out = M + logf(S);
    }
}

// ---------------------------------------------------------------------------
// Kernel 2: single block. Entity gathers + LSE difference, double reduction.
// ---------------------------------------------------------------------------
__global__ void __launch_bounds__(NTHREADS)
finalize_kernel(const float* __restrict__ ori, const float* __restrict__ gen,
                const int* __restrict__ lens, const int* __restrict__ ents,
                int B0, int N, int E, float* __restrict__ out) {
    __shared__ int rep[256];
    const int tid = threadIdx.x;

    if (tid == 0) {
        int idx = 0;
        for (int b = 0; b < B0 && idx < N; b++) {
            int L = lens[b];
            for (int k = 0; k < L && idx < N; k++) rep[idx++] = b;
        }
        while (idx < N) rep[idx++] = B0 - 1;  // total_repeat_length padding
    }
    __syncthreads();

    // Part A: sum over (n, t, e) of gen gather minus ori gather.
    double accA = 0.0;
    const int totalA = N * T_DIM * E;
    for (int i = tid; i < totalA; i += NTHREADS) {
        int e = i % E;
        int t = (i / E) % T_DIM;
        int n = i / (E * T_DIM);
        int col = ents[n * E + e];
        float gv = gen[((size_t)n * T_DIM + t) * V_DIM + col];
        float ov = ori[((size_t)rep[n] * T_DIM + t) * V_DIM + col];
        accA += (double)gv - (double)ov;
    }

    // Part B: sum over (n, t) of lse_ori[rep[n],t] - lse_gen[n,t].
    double accB = 0.0;
    const int totalB = N * T_DIM;
    for (int i = tid; i < totalB; i += NTHREADS) {
        int t = i % T_DIM;
        int n = i / T_DIM;
        accB += (double)g_lse_ori[rep[n] * T_DIM + t] - (double)g_lse_gen[i];
    }

    double v = accA / ((double)N * (double)E * (double)T_DIM)
             + accB / ((double)N * (double)T_DIM);

    __shared__ double red[NTHREADS];
    red[tid] = v;
    __syncthreads();
    #pragma unroll
    for (int off = NTHREADS / 2; off; off >>= 1) {
        if (tid < off) red[tid] += red[tid + off];
        __syncthreads();
    }
    if (tid == 0) out[0] = (float)red[0];
}

// ---------------------------------------------------------------------------
extern "C" void kernel_launch(void* const* d_in, const int* in_sizes, int n_in,
                              void* d_out, int out_size) {
    const float* ori  = (const float*)d_in[0];  // [B0, T, V]
    const float* gen  = (const float*)d_in[1];  // [N,  T, V]
    const int*   lens = (const int*)d_in[2];    // [B0]
    const int*   ents = (const int*)d_in[3];    // [N, E]

    const int B0 = in_sizes[0] / (T_DIM * V_DIM);
    const int N  = in_sizes[1] / (T_DIM * V_DIM);
    const int E  = in_sizes[3] / N;

    lse_kernel<<<(B0 + N) * T_DIM, NTHREADS>>>(ori, gen, B0, N);
    finalize_kernel<<<1, NTHREADS>>>(ori, gen, lens, ents, B0, N, E,
                                     (float*)d_out);
}

// round 8
// speedup vs baseline: 1.2515x; 1.2515x over previous
#include <cuda_runtime.h>
#include <math_constants.h>

// NDE loss, fused:
//   Kernel 1: one block per (tensor-row). Computes logsumexp over V with
//   vectorized float4 streaming, then thread 0 folds in that row's full
//   contribution to the final scalar (entity gathers for gen rows, weighted
//   LSE for ori rows) and writes a per-row double to scratch.
//   Kernel 2: one block reduces the per-row doubles (fixed order, no atomics).
//
// out = (1/(N*E*T)) * sum_{n,t,e} ( gen[n,t,ent] - ori[rep[n],t,ent] )
//     + (1/(N*T))   * sum_{n,t}   ( lse_ori[rep[n],t] - lse_gen[n,t] )
//
// Bench shapes: B0=8, N=16, T=128, V=50257, E=4.

#define T_DIM 128
#define V_DIM 50257
#define NTHREADS 256
#define MAX_ROWS ((64 + 128) * T_DIM)

__device__ double g_contrib[MAX_ROWS];

__device__ __forceinline__ void lse_merge(float& m, float& s, float om, float os) {
    float nm = fmaxf(m, om);
    s = s * __expf(m - nm) + os * __expf(om - nm);
    m = nm;
}

// repeat_interleave(arange(B0), lens, total_repeat_length=N) semantics:
// truncate at N; pad with last element (B0-1) if sum < N.
__device__ __forceinline__ int rep_of(const int* lens, int B0, int N, int n) {
    int pre = 0;
    for (int b = 0; b < B0; b++) {
        int L = lens[b];
        if (n < pre + L) return b;
        pre += L;
    }
    return B0 - 1;  // padding
}

__global__ void __launch_bounds__(NTHREADS)
lse_gather_kernel(const float* __restrict__ ori, const float* __restrict__ gen,
                  const int* __restrict__ lens, const int* __restrict__ ents,
                  int B0, int N, int E) {
    const int row = blockIdx.x;
    const int oriRows = B0 * T_DIM;
    const bool isOri = row < oriRows;
    const int rr = isOri ? row : row - oriRows;
    const float* base = (isOri ? ori : gen) + (size_t)rr * V_DIM;

    const int tid = threadIdx.x;
    const int B = NTHREADS;

    float m = -CUDART_INF_F;
    float s = 0.0f;

    // ---- alignment peel to 16B ----
    const int peel = (int)((4u - (((size_t)rr * V_DIM) & 3u)) & 3u);
    if (tid < peel) {
        float x = base[tid];
        m = x;
        s = 1.0f;
    }
    const int n4 = (V_DIM - peel) >> 2;  // # of float4 in body
    const float4* __restrict__ p4 = reinterpret_cast<const float4*>(base + peel);

    // ---- body: 2 x float4 per thread per iteration (8 elems, 9 exps) ----
    int j = tid;
    for (; j + B < n4; j += 2 * B) {
        float4 a = p4[j];
        float4 b = p4[j + B];
        float lm = fmaxf(fmaxf(fmaxf(a.x, a.y), fmaxf(a.z, a.w)),
                         fmaxf(fmaxf(b.x, b.y), fmaxf(b.z, b.w)));
        float nm = fmaxf(m, lm);
        s = s * __expf(m - nm)
            + __expf(a.x - nm) + __expf(a.y - nm)
            + __expf(a.z - nm) + __expf(a.w - nm)
            + __expf(b.x - nm) + __expf(b.y - nm)
            + __expf(b.z - nm) + __expf(b.w - nm);
        m = nm;
    }
    if (j < n4) {
        float4 a = p4[j];
        float lm = fmaxf(fmaxf(a.x, a.y), fmaxf(a.z, a.w));
        float nm = fmaxf(m, lm);
        s = s * __expf(m - nm)
            + __expf(a.x - nm) + __expf(a.y - nm)
            + __expf(a.z - nm) + __expf(a.w - nm);
        m = nm;
    }
    // ---- scalar tail (< 4 elems) ----
    {
        const int done = peel + 4 * n4;
        const int tail = V_DIM - done;
        if (tid < tail) {
            float x = base[done + tid];
            float nm = fmaxf(m, x);
            s = s * __expf(m - nm) + __expf(x - nm);
            m = nm;
        }
    }

    // ---- warp merge ----
    const unsigned full = 0xffffffffu;
    #pragma unroll
    for (int off = 16; off; off >>= 1) {
        float om = __shfl_xor_sync(full, m, off);
        float os = __shfl_xor_sync(full, s, off);
        lse_merge(m, s, om, os);
    }

    __shared__ float shm[NTHREADS / 32];
    __shared__ float shs[NTHREADS / 32];
    const int wid = tid >> 5;
    if ((tid & 31) == 0) { shm[wid] = m; shs[wid] = s; }
    __syncthreads();

    if (tid == 0) {
        float M = shm[0], S = shs[0];
        #pragma unroll
        for (int w = 1; w < NTHREADS / 32; w++) lse_merge(M, S, shm[w], shs[w]);
        const double lse = (double)M + (double)logf(S);

        const double invNT = 1.0 / ((double)N * (double)T_DIM);
        double contrib;
        if (isOri) {
            // weight w_b = # of n with rep[n] == b (with jnp pad-with-last)
            const int b = rr / T_DIM;
            int pre = 0, total = 0;
            int w = 0;
            for (int k = 0; k < B0; k++) {
                int L = lens[k];
                if (k == b) {
                    int lo = pre < N ? pre : N;
                    int hi = (pre + L) < N ? (pre + L) : N;
                    w = hi - lo;
                }
                pre += L;
            }
            total = pre;
            if (b == B0 - 1 && total < N) w += N - total;
            contrib = lse * (double)w * invNT;
        } else {
            const int n = rr / T_DIM;
            const int t = rr % T_DIM;
            const int rep = rep_of(lens, B0, N, n);
            const float* orow = ori + ((size_t)rep * T_DIM + t) * V_DIM;
            const float* grow = gen + ((size_t)n * T_DIM + t) * V_DIM;
            double ga = 0.0;
            for (int e = 0; e < E; e++) {
                int col = ents[n * E + e];
                ga += (double)grow[col] - (double)orow[col];
            }
            contrib = ga * invNT / (double)E - lse * invNT;
        }
        g_contrib[row] = contrib;
    }
}

__global__ void __launch_bounds__(NTHREADS)
reduce_kernel(int totalRows, float* __restrict__ out) {
    const int tid = threadIdx.x;
    double acc = 0.0;
    for (int i = tid; i < totalRows; i += NTHREADS) acc += g_contrib[i];
    __shared__ double red[NTHREADS];
    red[tid] = acc;
    __syncthreads();
    #pragma unroll
    for (int off = NTHREADS / 2; off; off >>= 1) {
        if (tid < off) red[tid] += red[tid + off];
        __syncthreads();
    }
    if (tid == 0) out[0] = (float)red[0];
}

extern "C" void kernel_launch(void* const* d_in, const int* in_sizes, int n_in,
                              void* d_out, int out_size) {
    const float* ori  = (const float*)d_in[0];  // [B0, T, V]
    const float* gen  = (const float*)d_in[1];  // [N,  T, V]
    const int*   lens = (const int*)d_in[2];    // [B0]
    const int*   ents = (const int*)d_in[3];    // [N, E]

    const int B0 = in_sizes[0] / (T_DIM * V_DIM);
    const int N  = in_sizes[1] / (T_DIM * V_DIM);
    const int E  = in_sizes[3] / N;
    const int totalRows = (B0 + N) * T_DIM;

    lse_gather_kernel<<<totalRows, NTHREADS>>>(ori, gen, lens, ents, B0, N, E);
    reduce_kernel<<<1, NTHREADS>>>(totalRows, (float*)d_out);
}

// round 9
// speedup vs baseline: 1.3309x; 1.0635x over previous
#include <cuda_runtime.h>
#include <math_constants.h>

// NDE loss, single fused kernel:
//   One block per (tensor-row) of ori [B0*T rows] then gen [N*T rows].
//   Each block: streaming logsumexp over V (4 x float4 per thread per iter,
//   __ldcs evict-streaming, one exp-rescale per 16 elements), then thread 0
//   folds the row's full contribution (entity gathers for gen rows, weighted
//   LSE for ori rows) into a per-row double. The LAST block to finish
//   (fence + atomic counter) reduces all per-row doubles in fixed order and
//   writes the scalar, then resets the counter (graph-replay safe).
//
// out = (1/(N*E*T)) * sum_{n,t,e} ( gen[n,t,ent] - ori[rep[n],t,ent] )
//     + (1/(N*T))   * sum_{n,t}   ( lse_ori[rep[n],t] - lse_gen[n,t] )
//
// Bench shapes: B0=8, N=16, T=128, V=50257, E=4.

#define T_DIM 128
#define V_DIM 50257
#define NTHREADS 256
#define MAX_ROWS ((64 + 128) * T_DIM)

__device__ double g_contrib[MAX_ROWS];
__device__ unsigned int g_done_count;  // zero-initialized; reset by last block

__device__ __forceinline__ void lse_merge(float& m, float& s, float om, float os) {
    float nm = fmaxf(m, om);
    s = s * __expf(m - nm) + os * __expf(om - nm);
    m = nm;
}

__device__ __forceinline__ float max4(float4 a) {
    return fmaxf(fmaxf(a.x, a.y), fmaxf(a.z, a.w));
}
__device__ __forceinline__ float expsum4(float4 a, float nm) {
    return __expf(a.x - nm) + __expf(a.y - nm) + __expf(a.z - nm) + __expf(a.w - nm);
}

// repeat_interleave(arange(B0), lens, total_repeat_length=N):
// truncate at N; pad with last element (B0-1) if sum < N.
__device__ __forceinline__ int rep_of(const int* lens, int B0, int N, int n) {
    int pre = 0;
    for (int b = 0; b < B0; b++) {
        int L = lens[b];
        if (n < pre + L) return b;
        pre += L;
    }
    return B0 - 1;
}

__global__ void __launch_bounds__(NTHREADS)
nde_fused_kernel(const float* __restrict__ ori, const float* __restrict__ gen,
                 const int* __restrict__ lens, const int* __restrict__ ents,
                 int B0, int N, int E, float* __restrict__ out) {
    const int row = blockIdx.x;
    const int totalRows = gridDim.x;
    const int oriRows = B0 * T_DIM;
    const bool isOri = row < oriRows;
    const int rr = isOri ? row : row - oriRows;
    const float* base = (isOri ? ori : gen) + (size_t)rr * V_DIM;

    const int tid = threadIdx.x;
    const int B = NTHREADS;

    float m = -CUDART_INF_F;
    float s = 0.0f;

    // ---- alignment peel to 16B ----
    const int peel = (int)((4u - (((size_t)rr * (size_t)V_DIM) & 3u)) & 3u);
    if (tid < peel) {
        m = base[tid];
        s = 1.0f;
    }
    const int n4 = (V_DIM - peel) >> 2;
    const float4* __restrict__ p4 = reinterpret_cast<const float4*>(base + peel);

    // ---- body: 4 x float4 per thread per iteration (16 elems, 17 exps) ----
    int j = tid;
    for (; j + 3 * B < n4; j += 4 * B) {
        float4 a = __ldcs(&p4[j]);
        float4 b = __ldcs(&p4[j + B]);
        float4 c = __ldcs(&p4[j + 2 * B]);
        float4 d = __ldcs(&p4[j + 3 * B]);
        float lm = fmaxf(fmaxf(max4(a), max4(b)), fmaxf(max4(c), max4(d)));
        float nm = fmaxf(m, lm);
        s = s * __expf(m - nm)
            + expsum4(a, nm) + expsum4(b, nm) + expsum4(c, nm) + expsum4(d, nm);
        m = nm;
    }
    for (; j < n4; j += B) {
        float4 a = __ldcs(&p4[j]);
        float nm = fmaxf(m, max4(a));
        s = s * __expf(m - nm) + expsum4(a, nm);
        m = nm;
    }
    // ---- scalar tail (< 4 elems) ----
    {
        const int done = peel + 4 * n4;
        const int tail = V_DIM - done;
        if (tid < tail) {
            float x = base[done + tid];
            float nm = fmaxf(m, x);
            s = s * __expf(m - nm) + __expf(x - nm);
            m = nm;
        }
    }

    // ---- warp merge ----
    const unsigned full = 0xffffffffu;
    #pragma unroll
    for (int off = 16; off; off >>= 1) {
        float om = __shfl_xor_sync(full, m, off);
        float os = __shfl_xor_sync(full, s, off);
        lse_merge(m, s, om, os);
    }

    __shared__ float shm[NTHREADS / 32];
    __shared__ float shs[NTHREADS / 32];
    __shared__ bool sh_last;
    const int wid = tid >> 5;
    if ((tid & 31) == 0) { shm[wid] = m; shs[wid] = s; }
    __syncthreads();

    if (tid == 0) {
        float M = shm[0], S = shs[0];
        #pragma unroll
        for (int w = 1; w < NTHREADS / 32; w++) lse_merge(M, S, shm[w], shs[w]);
        const double lse = (double)M + (double)logf(S);

        const double invNT = 1.0 / ((double)N * (double)T_DIM);
        double contrib;
        if (isOri) {
            // weight w_b = # of n with rep[n] == b (jnp pad-with-last semantics)
            const int b = rr / T_DIM;
            int pre = 0, w = 0;
            for (int k = 0; k < B0; k++) {
                int L = lens[k];
                if (k == b) {
                    int lo = pre < N ? pre : N;
                    int hi = (pre + L) < N ? (pre + L) : N;
                    w = hi - lo;
                }
                pre += L;
            }
            if (b == B0 - 1 && pre < N) w += N - pre;
            contrib = lse * (double)w * invNT;
        } else {
            const int n = rr / T_DIM;
            const int t = rr % T_DIM;
            const int rep = rep_of(lens, B0, N, n);
            const float* orow = ori + ((size_t)rep * T_DIM + t) * V_DIM;
            const float* grow = gen + ((size_t)n * T_DIM + t) * V_DIM;
            double ga = 0.0;
            for (int e = 0; e < E; e++) {
                int col = ents[n * E + e];
                ga += (double)grow[col] - (double)orow[col];
            }
            contrib = ga * invNT / (double)E - lse * invNT;
        }
        g_contrib[row] = contrib;
        __threadfence();
        unsigned prev = atomicInc(&g_done_count, 0xffffffffu);
        sh_last = (prev == (unsigned)(totalRows - 1));
    }
    __syncthreads();

    // ---- last block: deterministic fixed-order reduction of per-row doubles
    if (sh_last) {
        double acc = 0.0;
        for (int i = tid; i < totalRows; i += NTHREADS) acc += g_contrib[i];
        __shared__ double red[NTHREADS];
        red[tid] = acc;
        __syncthreads();
        #pragma unroll
        for (int off = NTHREADS / 2; off; off >>= 1) {
            if (tid < off) red[tid] += red[tid + off];
            __syncthreads();
        }
        if (tid == 0) {
            out[0] = (float)red[0];
            g_done_count = 0;  // reset for next graph replay
        }
    }
}

extern "C" void kernel_launch(void* const* d_in, const int* in_sizes, int n_in,
                              void* d_out, int out_size) {
    const float* ori  = (const float*)d_in[0];  // [B0, T, V]
    const float* gen  = (const float*)d_in[1];  // [N,  T, V]
    const int*   lens = (const int*)d_in[2];    // [B0]
    const int*   ents = (const int*)d_in[3];    // [N, E]

    const int B0 = in_sizes[0] / (T_DIM * V_DIM);
    const int N  = in_sizes[1] / (T_DIM * V_DIM);
    const int E  = in_sizes[3] / N;
    const int totalRows = (B0 + N) * T_DIM;

    nde_fused_kernel<<<totalRows, NTHREADS>>>(ori, gen, lens, ents, B0, N, E,
                                              (float*)d_out);
}

// round 10
// speedup vs baseline: 1.3313x; 1.0003x over previous
#include <cuda_runtime.h>
#include <math_constants.h>

// NDE loss, single fused kernel:
//   One block per (tensor-row) of ori [B0*T rows] then gen [N*T rows].
//   Each block: streaming logsumexp over V (4 x float4 per thread per iter,
//   __ldcs evict-streaming, one exp-rescale per 16 elements), then thread 0
//   folds the row's full contribution (entity gathers for gen rows, weighted
//   LSE for ori rows) into a per-row double. The LAST block to finish
//   (fence + atomic counter) reduces all per-row doubles in fixed order and
//   writes the scalar, then resets the counter (graph-replay safe).
//
// out = (1/(N*E*T)) * sum_{n,t,e} ( gen[n,t,ent] - ori[rep[n],t,ent] )
//     + (1/(N*T))   * sum_{n,t}   ( lse_ori[rep[n],t] - lse_gen[n,t] )
//
// Bench shapes: B0=8, N=16, T=128, V=50257, E=4.

#define T_DIM 128
#define V_DIM 50257
#define NTHREADS 256
#define MAX_ROWS ((64 + 128) * T_DIM)

__device__ double g_contrib[MAX_ROWS];
__device__ unsigned int g_done_count;  // zero-initialized; reset by last block

__device__ __forceinline__ void lse_merge(float& m, float& s, float om, float os) {
    float nm = fmaxf(m, om);
    s = s * __expf(m - nm) + os * __expf(om - nm);
    m = nm;
}

__device__ __forceinline__ float max4(float4 a) {
    return fmaxf(fmaxf(a.x, a.y), fmaxf(a.z, a.w));
}
__device__ __forceinline__ float expsum4(float4 a, float nm) {
    return __expf(a.x - nm) + __expf(a.y - nm) + __expf(a.z - nm) + __expf(a.w - nm);
}

// repeat_interleave(arange(B0), lens, total_repeat_length=N):
// truncate at N; pad with last element (B0-1) if sum < N.
__device__ __forceinline__ int rep_of(const int* lens, int B0, int N, int n) {
    int pre = 0;
    for (int b = 0; b < B0; b++) {
        int L = lens[b];
        if (n < pre + L) return b;
        pre += L;
    }
    return B0 - 1;
}

__global__ void __launch_bounds__(NTHREADS)
nde_fused_kernel(const float* __restrict__ ori, const float* __restrict__ gen,
                 const int* __restrict__ lens, const int* __restrict__ ents,
                 int B0, int N, int E, float* __restrict__ out) {
    const int row = blockIdx.x;
    const int totalRows = gridDim.x;
    const int oriRows = B0 * T_DIM;
    const bool isOri = row < oriRows;
    const int rr = isOri ? row : row - oriRows;
    const float* base = (isOri ? ori : gen) + (size_t)rr * V_DIM;

    const int tid = threadIdx.x;
    const int B = NTHREADS;

    float m = -CUDART_INF_F;
    float s = 0.0f;

    // ---- alignment peel to 16B ----
    const int peel = (int)((4u - (((size_t)rr * (size_t)V_DIM) & 3u)) & 3u);
    if (tid < peel) {
        m = base[tid];
        s = 1.0f;
    }
    const int n4 = (V_DIM - peel) >> 2;
    const float4* __restrict__ p4 = reinterpret_cast<const float4*>(base + peel);

    // ---- body: 4 x float4 per thread per iteration (16 elems, 17 exps) ----
    int j = tid;
    for (; j + 3 * B < n4; j += 4 * B) {
        float4 a = __ldcs(&p4[j]);
        float4 b = __ldcs(&p4[j + B]);
        float4 c = __ldcs(&p4[j + 2 * B]);
        float4 d = __ldcs(&p4[j + 3 * B]);
        float lm = fmaxf(fmaxf(max4(a), max4(b)), fmaxf(max4(c), max4(d)));
        float nm = fmaxf(m, lm);
        s = s * __expf(m - nm)
            + expsum4(a, nm) + expsum4(b, nm) + expsum4(c, nm) + expsum4(d, nm);
        m = nm;
    }
    for (; j < n4; j += B) {
        float4 a = __ldcs(&p4[j]);
        float nm = fmaxf(m, max4(a));
        s = s * __expf(m - nm) + expsum4(a, nm);
        m = nm;
    }
    // ---- scalar tail (< 4 elems) ----
    {
        const int done = peel + 4 * n4;
        const int tail = V_DIM - done;
        if (tid < tail) {
            float x = base[done + tid];
            float nm = fmaxf(m, x);
            s = s * __expf(m - nm) + __expf(x - nm);
            m = nm;
        }
    }

    // ---- warp merge ----
    const unsigned full = 0xffffffffu;
    #pragma unroll
    for (int off = 16; off; off >>= 1) {
        float om = __shfl_xor_sync(full, m, off);
        float os = __shfl_xor_sync(full, s, off);
        lse_merge(m, s, om, os);
    }

    __shared__ float shm[NTHREADS / 32];
    __shared__ float shs[NTHREADS / 32];
    __shared__ bool sh_last;
    const int wid = tid >> 5;
    if ((tid & 31) == 0) { shm[wid] = m; shs[wid] = s; }
    __syncthreads();

    if (tid == 0) {
        float M = shm[0], S = shs[0];
        #pragma unroll
        for (int w = 1; w < NTHREADS / 32; w++) lse_merge(M, S, shm[w], shs[w]);
        const double lse = (double)M + (double)logf(S);

        const double invNT = 1.0 / ((double)N * (double)T_DIM);
        double contrib;
        if (isOri) {
            // weight w_b = # of n with rep[n] == b (jnp pad-with-last semantics)
            const int b = rr / T_DIM;
            int pre = 0, w = 0;
            for (int k = 0; k < B0; k++) {
                int L = lens[k];
                if (k == b) {
                    int lo = pre < N ? pre : N;
                    int hi = (pre + L) < N ? (pre + L) : N;
                    w = hi - lo;
                }
                pre += L;
            }
            if (b == B0 - 1 && pre < N) w += N - pre;
            contrib = lse * (double)w * invNT;
        } else {
            const int n = rr / T_DIM;
            const int t = rr % T_DIM;
            const int rep = rep_of(lens, B0, N, n);
            const float* orow = ori + ((size_t)rep * T_DIM + t) * V_DIM;
            const float* grow = gen + ((size_t)n * T_DIM + t) * V_DIM;
            double ga = 0.0;
            for (int e = 0; e < E; e++) {
                int col = ents[n * E + e];
                ga += (double)grow[col] - (double)orow[col];
            }
            contrib = ga * invNT / (double)E - lse * invNT;
        }
        g_contrib[row] = contrib;
        __threadfence();
        unsigned prev = atomicInc(&g_done_count, 0xffffffffu);
        sh_last = (prev == (unsigned)(totalRows - 1));
    }
    __syncthreads();

    // ---- last block: deterministic fixed-order reduction of per-row doubles
    if (sh_last) {
        double acc = 0.0;
        for (int i = tid; i < totalRows; i += NTHREADS) acc += g_contrib[i];
        __shared__ double red[NTHREADS];
        red[tid] = acc;
        __syncthreads();
        #pragma unroll
        for (int off = NTHREADS / 2; off; off >>= 1) {
            if (tid < off) red[tid] += red[tid + off];
            __syncthreads();
        }
        if (tid == 0) {
            out[0] = (float)red[0];
            g_done_count = 0;  // reset for next graph replay
        }
    }
}

extern "C" void kernel_launch(void* const* d_in, const int* in_sizes, int n_in,
                              void* d_out, int out_size) {
    const float* ori  = (const float*)d_in[0];  // [B0, T, V]
    const float* gen  = (const float*)d_in[1];  // [N,  T, V]
    const int*   lens = (const int*)d_in[2];    // [B0]
    const int*   ents = (const int*)d_in[3];    // [N, E]

    const int B0 = in_sizes[0] / (T_DIM * V_DIM);
    const int N  = in_sizes[1] / (T_DIM * V_DIM);
    const int E  = in_sizes[3] / N;
    const int totalRows = (B0 + N) * T_DIM;

    nde_fused_kernel<<<totalRows, NTHREADS>>>(ori, gen, lens, ents, B0, N, E,
                                              (float*)d_out);
}